// round 13
// baseline (speedup 1.0000x reference)
#include <cuda_runtime.h>
#include <cstdint>

#define BS 32
#define NN 1024
#define FO 128
#define NWORDS 32

#define RW 2                   // rows per warp
#define BW 2                   // batches per block (interleaved float2)
#define WARPS 4                // 128 threads
#define ROWS_PER_BLOCK 8       // RW * WARPS
#define PACK_BLOCKS 512

typedef unsigned long long ull;

// Scratch (no allocations allowed)
__device__ uint32_t g_adjw[NN * NWORDS];   // 128 KB packed adjacency

// ---------------------------------------------------------------------------
// Setup: pack-only (proven fast path). 512 blocks x 256 threads.
// ---------------------------------------------------------------------------
__global__ void __launch_bounds__(256) k_setup(const int* __restrict__ adj) {
    int tid = threadIdx.x;
    int t = blockIdx.x * 256 + tid;
    const int4* a4 = reinterpret_cast<const int4*>(adj);
    int4 v0 = a4[2 * t];
    int4 v1 = a4[2 * t + 1];
    uint32_t m = 0;
    m |= (v0.x > 0) ? 1u   : 0u;
    m |= (v0.y > 0) ? 2u   : 0u;
    m |= (v0.z > 0) ? 4u   : 0u;
    m |= (v0.w > 0) ? 8u   : 0u;
    m |= (v1.x > 0) ? 16u  : 0u;
    m |= (v1.y > 0) ? 32u  : 0u;
    m |= (v1.z > 0) ? 64u  : 0u;
    m |= (v1.w > 0) ? 128u : 0u;
    int lane = tid & 31;
    uint32_t val = m << ((lane & 3) * 8);
    val |= __shfl_xor_sync(0xffffffffu, val, 1);
    val |= __shfl_xor_sync(0xffffffffu, val, 2);
    uint32_t w = __shfl_sync(0xffffffffu, val, (lane & 7) * 4);
    int wbase = (t >> 5) * 8;
    if (lane < 8) g_adjw[wbase + lane] = w;
}

// ---------------------------------------------------------------------------
// Main: 2048 blocks x 128 thr (R11 config). Warp = 2 rows x 2 batches.
// New: float2-interleaved x (one LDS.64 serves both batches), packed f32x2
// accumulators (FSETP + @p ADD2 per pair), scalars computed in-prologue.
// Keep-predicate identical: adj bit && (c2*x_j > -c1*x_i).
// ---------------------------------------------------------------------------
__device__ __forceinline__ float elu_fast(float v) {
    return v > 0.f ? v : (__expf(v) - 1.0f);
}

// One row vs 2 batches: bp = (wr != 0), then per batch
// kp = (s2_b > thr_b) && bp ; @kp acc_b += packed {e2, e2x}.
#define ROW_ACC2(ACC0, ACC1, WR, S0, T0, Q0, S1, T1, Q1)    \
    asm ("{\n\t"                                            \
         ".reg .pred bp, kp;\n\t"                           \
         "setp.ne.u32 bp, %2, 0;\n\t"                       \
         "setp.gt.and.f32 kp, %3, %4, bp;\n\t"              \
         "@kp add.rn.f32x2 %0, %0, %5;\n\t"                 \
         "setp.gt.and.f32 kp, %6, %7, bp;\n\t"              \
         "@kp add.rn.f32x2 %1, %1, %8;\n\t"                 \
         "}"                                                \
         : "+l"(ACC0), "+l"(ACC1)                           \
         : "r"(WR),                                         \
           "f"(S0), "f"(T0), "l"(Q0),                       \
           "f"(S1), "f"(T1), "l"(Q1))

__global__ void __launch_bounds__(128, 12) k_main(const float* __restrict__ x,
                                                  const float* __restrict__ W,
                                                  const float* __restrict__ a,
                                                  float* __restrict__ out) {
    __shared__ float2   s_xi[NN];                        // 8 KB {x_b0, x_b1}
    __shared__ uint32_t s_adjT[NWORDS][ROWS_PER_BLOCK];  // 1 KB [word][row]
    __shared__ float    s_W[FO];                         // 512 B
    __shared__ float    s_scr[WARPS][4];                 // reduce scratch

    int tid  = threadIdx.x;
    int lane = tid & 31;
    int warp = tid >> 5;
    int row0 = blockIdx.x * ROWS_PER_BLOCK;
    int b0   = blockIdx.y * BW;

    // ---- cooperative loads ----
    {
        const float4* x0 = reinterpret_cast<const float4*>(x + (size_t)b0 * NN);
        const float4* x1 = reinterpret_cast<const float4*>(x + (size_t)(b0 + 1) * NN);
        for (int t = tid; t < NN / 4; t += 128) {
            float4 u = x0[t], v = x1[t];
            int j = t * 4;
            s_xi[j]     = make_float2(u.x, v.x);
            s_xi[j + 1] = make_float2(u.y, v.y);
            s_xi[j + 2] = make_float2(u.z, v.z);
            s_xi[j + 3] = make_float2(u.w, v.w);
        }
    }
    {
        int r = tid >> 5, kk = tid & 31;
        s_adjT[kk][r]     = g_adjw[(row0 + r) * NWORDS + kk];
        s_adjT[kk][r + 4] = g_adjw[(row0 + r + 4) * NWORDS + kk];
    }
    float wv_t = W[tid];
    s_W[tid] = wv_t;

    // c1/c2 partials (independent of smem)
    float p1 = wv_t * a[tid];
    float p2 = wv_t * a[FO + tid];
    __syncthreads();

    // per-batch mean partials from s_xi
    float m0 = 0.f, m1 = 0.f;
    for (int t = tid; t < NN; t += 128) {
        float2 v = s_xi[t];
        m0 += v.x; m1 += v.y;
    }
#pragma unroll
    for (int o = 16; o > 0; o >>= 1) {
        p1 += __shfl_xor_sync(0xffffffffu, p1, o);
        p2 += __shfl_xor_sync(0xffffffffu, p2, o);
        m0 += __shfl_xor_sync(0xffffffffu, m0, o);
        m1 += __shfl_xor_sync(0xffffffffu, m1, o);
    }
    if (lane == 0) {
        s_scr[warp][0] = p1; s_scr[warp][1] = p2;
        s_scr[warp][2] = m0; s_scr[warp][3] = m1;
    }
    __syncthreads();
    const float c1 = s_scr[0][0] + s_scr[1][0] + s_scr[2][0] + s_scr[3][0];
    const float c2 = s_scr[0][1] + s_scr[1][1] + s_scr[2][1] + s_scr[3][1];
    const float mean0 = (s_scr[0][2] + s_scr[1][2] + s_scr[2][2] + s_scr[3][2]) * (1.0f / NN);
    const float mean1 = (s_scr[0][3] + s_scr[1][3] + s_scr[2][3] + s_scr[3][3]) * (1.0f / NN);

    const int ir = warp * RW;
    const uint32_t lanebit = 1u << lane;

    // thresholds: thr = -c1 * x_i (per row, per batch) — one LDS.64 per row
    float thr[RW][BW];
#pragma unroll
    for (int r = 0; r < RW; r++) {
        float2 xi = s_xi[row0 + ir + r];
        thr[r][0] = -c1 * xi.x;
        thr[r][1] = -c1 * xi.y;
    }

    ull acc[RW][BW];   // packed {den (lo), num (hi)}
#pragma unroll
    for (int r = 0; r < RW; r++)
#pragma unroll
        for (int b = 0; b < BW; b++) acc[r][b] = 0ull;

#pragma unroll 8
    for (int kk = 0; kk < NWORDS; kk++) {
        uint2 w2 = *reinterpret_cast<const uint2*>(&s_adjT[kk][ir]);  // LDS.64
        uint32_t wr0 = w2.x & lanebit;
        uint32_t wr1 = w2.y & lanebit;
        float2 xv = s_xi[kk * 32 + lane];                             // LDS.64

        float s2_0 = c2 * xv.x;
        float e0   = __expf(s2_0);
        float2 q0f = make_float2(e0, e0 * xv.x);
        ull q0 = *reinterpret_cast<ull*>(&q0f);

        float s2_1 = c2 * xv.y;
        float e1   = __expf(s2_1);
        float2 q1f = make_float2(e1, e1 * xv.y);
        ull q1 = *reinterpret_cast<ull*>(&q1f);

        ROW_ACC2(acc[0][0], acc[0][1], wr0, s2_0, thr[0][0], q0, s2_1, thr[0][1], q1);
        ROW_ACC2(acc[1][0], acc[1][1], wr1, s2_0, thr[1][0], q0, s2_1, thr[1][1], q1);
    }

    const float4 wv = reinterpret_cast<const float4*>(s_W)[lane];

#pragma unroll
    for (int r = 0; r < RW; r++) {
        int i = row0 + ir + r;
#pragma unroll
        for (int b = 0; b < BW; b++) {
            ull aa = acc[r][b];
            float d  = __uint_as_float((uint32_t)(aa & 0xffffffffull));
            float nm = __uint_as_float((uint32_t)(aa >> 32));
#pragma unroll
            for (int o = 16; o > 0; o >>= 1) {
                d  += __shfl_xor_sync(0xffffffffu, d,  o);
                nm += __shfl_xor_sync(0xffffffffu, nm, o);
            }
            float y = (d > 0.f) ? __fdividef(nm, d) : (b == 0 ? mean0 : mean1);
            float4 z;
            z.x = elu_fast(y * wv.x);
            z.y = elu_fast(y * wv.y);
            z.z = elu_fast(y * wv.z);
            z.w = elu_fast(y * wv.w);
            reinterpret_cast<float4*>(out)[((size_t)(b0 + b) * NN + i) * (FO / 4) + lane] = z;
        }
    }
}

// ---------------------------------------------------------------------------
// Inputs per metadata order: input, adj, ext_input, side_input, W, a
// ---------------------------------------------------------------------------
extern "C" void kernel_launch(void* const* d_in, const int* in_sizes, int n_in,
                              void* d_out, int out_size) {
    const float* input = (const float*)d_in[0];
    const int*   adj   = (const int*)  d_in[1];
    const float* W     = (const float*)d_in[4];
    const float* a     = (const float*)d_in[5];
    float* out = (float*)d_out;

    k_setup<<<PACK_BLOCKS, 256>>>(adj);
    k_main<<<dim3(NN / ROWS_PER_BLOCK, BS / BW), 128>>>(input, W, a, out);
}

// round 14
// speedup vs baseline: 1.2280x; 1.2280x over previous
#include <cuda_runtime.h>
#include <cstdint>

#define BS 32
#define NN 1024
#define FO 128
#define NWORDS 32

#define RW 4                   // rows per warp
#define BW 2                   // batches per block
#define WARPS 4                // 128 threads
#define ROWS_PER_BLOCK 16      // RW * WARPS
#define PACK_BLOCKS 512

// Scratch (no allocations allowed)
__device__ uint32_t g_adjw[NN * NWORDS];   // 128 KB packed adjacency
__device__ float    g_c1, g_c2;
__device__ float    g_meanx[BS];

// ---------------------------------------------------------------------------
// Setup (R11-proven): pack adj via 2x LDG.128/thread + shfl byte-pack;
// per-batch mean(x); scalars c1, c2.
// ---------------------------------------------------------------------------
__global__ void __launch_bounds__(256) k_setup(const int* __restrict__ adj,
                                               const float* __restrict__ x,
                                               const float* __restrict__ W,
                                               const float* __restrict__ a) {
    int bid = blockIdx.x;
    int tid = threadIdx.x;

    if (bid < PACK_BLOCKS) {
        int t = bid * 256 + tid;
        const int4* a4 = reinterpret_cast<const int4*>(adj);
        int4 v0 = a4[2 * t];
        int4 v1 = a4[2 * t + 1];
        uint32_t m = 0;
        m |= (v0.x > 0) ? 1u   : 0u;
        m |= (v0.y > 0) ? 2u   : 0u;
        m |= (v0.z > 0) ? 4u   : 0u;
        m |= (v0.w > 0) ? 8u   : 0u;
        m |= (v1.x > 0) ? 16u  : 0u;
        m |= (v1.y > 0) ? 32u  : 0u;
        m |= (v1.z > 0) ? 64u  : 0u;
        m |= (v1.w > 0) ? 128u : 0u;
        int lane = tid & 31;
        uint32_t val = m << ((lane & 3) * 8);
        val |= __shfl_xor_sync(0xffffffffu, val, 1);
        val |= __shfl_xor_sync(0xffffffffu, val, 2);
        uint32_t w = __shfl_sync(0xffffffffu, val, (lane & 7) * 4);
        int wbase = (t >> 5) * 8;
        if (lane < 8) g_adjw[wbase + lane] = w;
        return;
    }

    __shared__ float red[256];

    if (bid < PACK_BLOCKS + BS) {
        int b = bid - PACK_BLOCKS;
        float s = 0.f;
        for (int n = tid; n < NN; n += 256) s += x[(size_t)b * NN + n];
        red[tid] = s; __syncthreads();
        for (int st = 128; st > 0; st >>= 1) {
            if (tid < st) red[tid] += red[tid + st];
            __syncthreads();
        }
        if (tid == 0) g_meanx[b] = red[0] * (1.0f / NN);
        return;
    }

    float p = (tid < FO) ? W[tid] * a[tid] : 0.f;
    red[tid] = p; __syncthreads();
    for (int st = 128; st > 0; st >>= 1) {
        if (tid < st) red[tid] += red[tid + st];
        __syncthreads();
    }
    if (tid == 0) g_c1 = red[0];
    __syncthreads();

    p = (tid < FO) ? W[tid] * a[FO + tid] : 0.f;
    red[tid] = p; __syncthreads();
    for (int st = 128; st > 0; st >>= 1) {
        if (tid < st) red[tid] += red[tid + st];
        __syncthreads();
    }
    if (tid == 0) g_c2 = red[0];
}

// ---------------------------------------------------------------------------
// Main: 1024 blocks x 128 thr, all resident in one wave. Warp = 4 rows x
// 2 batches: adj LDS.128 serves 4 rows; each exp serves 4 pairs.
// R11 loop semantics byte-for-byte: adj bit && (c2*x_j > -c1*x_i).
// ---------------------------------------------------------------------------
__device__ __forceinline__ float elu_fast(float v) {
    return v > 0.f ? v : (__expf(v) - 1.0f);
}

__global__ void __launch_bounds__(128, 8) k_main(const float* __restrict__ x,
                                                 const float* __restrict__ W,
                                                 float* __restrict__ out) {
    __shared__ float    s_x[BW][NN];                     // 8 KB
    __shared__ uint32_t s_adjT[NWORDS][ROWS_PER_BLOCK];  // 2 KB [word][row]
    __shared__ float    s_W[FO];                         // 512 B

    int tid  = threadIdx.x;
    int lane = tid & 31;
    int warp = tid >> 5;
    int row0 = blockIdx.x * ROWS_PER_BLOCK;
    int b0   = blockIdx.y * BW;

    // cooperative loads
    {
        const float4* src = reinterpret_cast<const float4*>(x + (size_t)b0 * NN);
        float4* dst = reinterpret_cast<float4*>(&s_x[0][0]);
        for (int t = tid; t < BW * NN / 4; t += 128) dst[t] = src[t];
    }
    for (int t = tid; t < ROWS_PER_BLOCK * NWORDS; t += 128) {
        int r = t >> 5, kk = t & 31;
        s_adjT[kk][r] = g_adjw[(row0 + r) * NWORDS + kk];
    }
    s_W[tid] = W[tid];
    __syncthreads();

    const float c1 = g_c1, c2 = g_c2;
    const int ir = warp * RW;
    const uint32_t lanebit = 1u << lane;

    float thr[RW][BW], den[RW][BW], num[RW][BW];
#pragma unroll
    for (int r = 0; r < RW; r++)
#pragma unroll
        for (int b = 0; b < BW; b++) {
            thr[r][b] = -c1 * s_x[b][row0 + ir + r];
            den[r][b] = 0.f;
            num[r][b] = 0.f;
        }

#pragma unroll 4
    for (int kk = 0; kk < NWORDS; kk++) {
        uint4 w4 = *reinterpret_cast<const uint4*>(&s_adjT[kk][ir]);  // LDS.128
        bool p0 = (w4.x & lanebit) != 0;
        bool p1 = (w4.y & lanebit) != 0;
        bool p2 = (w4.z & lanebit) != 0;
        bool p3 = (w4.w & lanebit) != 0;
#pragma unroll
        for (int b = 0; b < BW; b++) {
            float xv = s_x[b][kk * 32 + lane];
            float s2 = c2 * xv;
            float e2 = __expf(s2);
            if (p0 && (s2 > thr[0][b])) { den[0][b] += e2; num[0][b] = fmaf(e2, xv, num[0][b]); }
            if (p1 && (s2 > thr[1][b])) { den[1][b] += e2; num[1][b] = fmaf(e2, xv, num[1][b]); }
            if (p2 && (s2 > thr[2][b])) { den[2][b] += e2; num[2][b] = fmaf(e2, xv, num[2][b]); }
            if (p3 && (s2 > thr[3][b])) { den[3][b] += e2; num[3][b] = fmaf(e2, xv, num[3][b]); }
        }
    }

    const float4 wv = reinterpret_cast<const float4*>(s_W)[lane];

#pragma unroll
    for (int r = 0; r < RW; r++) {
        int i = row0 + ir + r;
#pragma unroll
        for (int b = 0; b < BW; b++) {
            float d = den[r][b], nm = num[r][b];
#pragma unroll
            for (int o = 16; o > 0; o >>= 1) {
                d  += __shfl_xor_sync(0xffffffffu, d,  o);
                nm += __shfl_xor_sync(0xffffffffu, nm, o);
            }
            float y = (d > 0.f) ? __fdividef(nm, d) : g_meanx[b0 + b];
            float4 z;
            z.x = elu_fast(y * wv.x);
            z.y = elu_fast(y * wv.y);
            z.z = elu_fast(y * wv.z);
            z.w = elu_fast(y * wv.w);
            reinterpret_cast<float4*>(out)[((size_t)(b0 + b) * NN + i) * (FO / 4) + lane] = z;
        }
    }
}

// ---------------------------------------------------------------------------
// Inputs per metadata order: input, adj, ext_input, side_input, W, a
// ---------------------------------------------------------------------------
extern "C" void kernel_launch(void* const* d_in, const int* in_sizes, int n_in,
                              void* d_out, int out_size) {
    const float* input = (const float*)d_in[0];
    const int*   adj   = (const int*)  d_in[1];
    const float* W     = (const float*)d_in[4];
    const float* a     = (const float*)d_in[5];
    float* out = (float*)d_out;

    k_setup<<<PACK_BLOCKS + BS + 1, 256>>>(adj, input, W, a);
    k_main<<<dim3(NN / ROWS_PER_BLOCK, BS / BW), 128>>>(input, W, out);
}